// round 1
// baseline (speedup 1.0000x reference)
#include <cuda_runtime.h>
#include <cuda_bf16.h>
#include <mma.h>

using namespace nvcuda;

// Problem constants
#define M_TOTAL   8192        // B*S = 4*2048
#define D_IN      4096
#define D_OUT     4096
#define R_TOTAL   128         // N_ADAPT * RANK = 8*16
#define LORA_SCALE 2.0f       // ALPHA/RANK = 32/16

// GEMM tiling
#define BM   128
#define BN   128
#define BK   32
#define LDK  36                // padded k-stride in smem (floats)
#define LDC  132               // padded epilogue row stride (floats)
#define SMEM_BYTES (BM * LDC * 4)   // 67584 B (epilogue dominates staging 2*BM*LDK*4=36864)

// Scratch (allocation-free): h = x @ A_all^T  [8192 x 128], Bc = scaled concat B [4096 x 128]
__device__ float g_h [M_TOTAL * R_TOTAL];
__device__ float g_Bc[D_OUT  * R_TOTAL];

// ---------------------------------------------------------------------------
// Bc[o][n*16+r] = lora_B[n][o][r] * (SCALE * lora_weights[n])
// ---------------------------------------------------------------------------
__global__ void build_bc_kernel(const float* __restrict__ lora_B,
                                const float* __restrict__ lw) {
    int i = blockIdx.x * 256 + threadIdx.x;
    if (i < D_OUT * R_TOTAL) {
        int o = i >> 7;         // output row
        int c = i & 127;        // concat column
        int n = c >> 4;
        int r = c & 15;
        g_Bc[i] = lora_B[((size_t)n * D_OUT + o) * 16 + r] * (LORA_SCALE * lw[n]);
    }
}

// ---------------------------------------------------------------------------
// Generic fused tf32 WMMA GEMM:
//   C[m0:m0+128, n0:n0+128] = A(lda) @ B(ldb)^T over K1
//                           + A2(lda2) @ B2(ldb2)^T over K2   (if K2>0)
//                           + bias                              (if bias)
// A is [M, K] row-major; B is [N, K] row-major (i.e. we compute A @ B^T).
// ---------------------------------------------------------------------------
__global__ __launch_bounds__(256, 2)
void wmma_gemm_kernel(const float* __restrict__ A,  int lda,
                      const float* __restrict__ B,  int ldb, int K1,
                      const float* __restrict__ A2, int lda2,
                      const float* __restrict__ B2, int ldb2, int K2,
                      const float* __restrict__ bias,
                      float* __restrict__ C, int ldc)
{
    extern __shared__ float smem[];
    float* As = smem;                 // [BM][LDK]
    float* Bs = smem + BM * LDK;      // [BN][LDK]

    const int tid    = threadIdx.x;
    const int wid    = tid >> 5;
    const int warp_m = wid >> 2;      // 0..1
    const int warp_n = wid & 3;       // 0..3
    const int m0     = blockIdx.y * BM;
    const int n0     = blockIdx.x * BN;

    wmma::fragment<wmma::accumulator, 16, 16, 8, float> acc[4][2];
    #pragma unroll
    for (int i = 0; i < 4; i++)
        #pragma unroll
        for (int j = 0; j < 2; j++)
            wmma::fill_fragment(acc[i][j], 0.0f);

    const int ldrow = tid >> 3;          // 0..31
    const int ldcol = (tid & 7) << 2;    // 0,4,...,28

    auto run = [&](const float* __restrict__ Ap, int la,
                   const float* __restrict__ Bp, int lb, int Kt) {
        for (int k0 = 0; k0 < Kt; k0 += BK) {
            // ---- stage A/B tiles (fully coalesced 128B segments) ----
            #pragma unroll
            for (int p = 0; p < 4; p++) {
                int r = ldrow + (p << 5);
                *reinterpret_cast<float4*>(&As[r * LDK + ldcol]) =
                    *reinterpret_cast<const float4*>(&Ap[(size_t)(m0 + r) * la + k0 + ldcol]);
                *reinterpret_cast<float4*>(&Bs[r * LDK + ldcol]) =
                    *reinterpret_cast<const float4*>(&Bp[(size_t)(n0 + r) * lb + k0 + ldcol]);
            }
            __syncthreads();

            // ---- 4 k-steps of m16n16k8 tf32 MMA ----
            #pragma unroll
            for (int kk = 0; kk < BK; kk += 8) {
                wmma::fragment<wmma::matrix_a, 16, 16, 8, wmma::precision::tf32, wmma::row_major> af[4];
                wmma::fragment<wmma::matrix_b, 16, 16, 8, wmma::precision::tf32, wmma::col_major> bf[2];
                #pragma unroll
                for (int i = 0; i < 4; i++) {
                    wmma::load_matrix_sync(af[i], &As[(warp_m * 64 + i * 16) * LDK + kk], LDK);
                    #pragma unroll
                    for (int e = 0; e < af[i].num_elements; e++)
                        af[i].x[e] = wmma::__float_to_tf32(af[i].x[e]);   // RNE, not truncate
                }
                #pragma unroll
                for (int j = 0; j < 2; j++) {
                    // Bs[n][k] row-major == (k,n) col-major with ldm=LDK
                    wmma::load_matrix_sync(bf[j], &Bs[(warp_n * 32 + j * 16) * LDK + kk], LDK);
                    #pragma unroll
                    for (int e = 0; e < bf[j].num_elements; e++)
                        bf[j].x[e] = wmma::__float_to_tf32(bf[j].x[e]);
                }
                #pragma unroll
                for (int i = 0; i < 4; i++)
                    #pragma unroll
                    for (int j = 0; j < 2; j++)
                        wmma::mma_sync(acc[i][j], af[i], bf[j], acc[i][j]);
            }
            __syncthreads();
        }
    };

    run(A, lda, B, ldb, K1);
    if (K2 > 0) run(A2, lda2, B2, ldb2, K2);

    // ---- epilogue: stage C in smem, fuse bias, coalesced float4 stores ----
    float* Cs = smem;   // [BM][LDC], reuses staging space (synced above)
    #pragma unroll
    for (int i = 0; i < 4; i++)
        #pragma unroll
        for (int j = 0; j < 2; j++)
            wmma::store_matrix_sync(&Cs[(warp_m * 64 + i * 16) * LDC + warp_n * 32 + j * 16],
                                    acc[i][j], LDC, wmma::mem_row_major);
    __syncthreads();

    #pragma unroll
    for (int p = 0; p < 16; p++) {
        int idx = tid + (p << 8);     // 0..4095 float4s of the 128x128 tile
        int r   = idx >> 5;
        int c   = (idx & 31) << 2;
        float4 v = *reinterpret_cast<float4*>(&Cs[r * LDC + c]);
        if (bias) {
            float4 bv = *reinterpret_cast<const float4*>(&bias[n0 + c]);
            v.x += bv.x; v.y += bv.y; v.z += bv.z; v.w += bv.w;
        }
        *reinterpret_cast<float4*>(&C[(size_t)(m0 + r) * ldc + n0 + c]) = v;
    }
}

// ---------------------------------------------------------------------------
// Harness entry. Inputs (metadata order): x, lora_A, lora_B, W, bias, lora_weights
// ---------------------------------------------------------------------------
extern "C" void kernel_launch(void* const* d_in, const int* in_sizes, int n_in,
                              void* d_out, int out_size)
{
    const float* x      = (const float*)d_in[0];   // [4,2048,4096]
    const float* lora_A = (const float*)d_in[1];   // [8,16,4096] == A_all [128,4096]
    const float* lora_B = (const float*)d_in[2];   // [8,4096,16]
    const float* W      = (const float*)d_in[3];   // [4096,4096]
    const float* bias   = (const float*)d_in[4];   // [4096]
    const float* lw     = (const float*)d_in[5];   // [8]
    float* out = (float*)d_out;                    // [4,2048,4096]

    cudaFuncSetAttribute(wmma_gemm_kernel,
                         cudaFuncAttributeMaxDynamicSharedMemorySize, SMEM_BYTES);

    float *h_ptr = nullptr, *bc_ptr = nullptr;
    cudaGetSymbolAddress((void**)&h_ptr,  g_h);
    cudaGetSymbolAddress((void**)&bc_ptr, g_Bc);

    // 1) Bc = scaled concat of lora_B
    build_bc_kernel<<<(D_OUT * R_TOTAL + 255) / 256, 256>>>(lora_B, lw);

    // 2) h = x @ A_all^T   [8192 x 128], single N-tile
    wmma_gemm_kernel<<<dim3(1, M_TOTAL / BM), 256, SMEM_BYTES>>>(
        x, D_IN, lora_A, D_IN, D_IN,
        nullptr, 0, nullptr, 0, 0,
        nullptr,
        h_ptr, R_TOTAL);

    // 3) out = x @ W^T (K=4096) + h @ Bc^T (K=128) + bias
    wmma_gemm_kernel<<<dim3(D_OUT / BN, M_TOTAL / BM), 256, SMEM_BYTES>>>(
        x, D_IN, W, D_IN, D_IN,
        h_ptr, R_TOTAL, bc_ptr, R_TOTAL, R_TOTAL,
        bias,
        out, D_OUT);
}

// round 3
// speedup vs baseline: 2.1273x; 2.1273x over previous
#include <cuda_runtime.h>
#include <cstdint>

// ---------------- problem constants ----------------
#define M_TOTAL 8192
#define DI      4096
#define DO      4096
#define RT      128          // 8 adapters * rank 16
#define LORA_SCALE 2.0f      // alpha/rank

// ---------------- GEMM tiling ----------------
#define BM 128
#define BN 128
#define BK 32
#define STAGES 4
#define LDK 36                        // padded row stride (floats)
#define ST_FLOATS (BM * LDK)          // 4608 floats per (A or B) stage
#define SMEM_FLOATS (STAGES * 2 * ST_FLOATS)
#define SMEM_BYTES (SMEM_FLOATS * 4)  // 147456

// ---------------- scratch (allocation-free) ----------------
__device__ float g_xr  [(size_t)M_TOTAL * DI];   // x rounded to tf32 (RNE)
__device__ float g_Weff[(size_t)DO * DI];        // W + Bc@A_all, rounded to tf32
__device__ float g_Bc  [DO * RT];                // scaled lora_B, tf32
__device__ float g_At  [DI * RT];                // A_all^T, tf32

// ---------------- helpers ----------------
__device__ __forceinline__ uint32_t smem_u32(const void* p) {
    uint32_t a;
    asm("{ .reg .u64 t; cvta.to.shared.u64 t, %1; cvt.u32.u64 %0, t; }" : "=r"(a) : "l"(p));
    return a;
}
__device__ __forceinline__ float rne_tf32(float v) {
    float r; asm("cvt.rna.tf32.f32 %0, %1;" : "=f"(r) : "f"(v)); return r;
}

#define CP_ASYNC16(dst, src) \
    asm volatile("cp.async.cg.shared.global [%0], [%1], 16;" :: "r"(dst), "l"(src) : "memory")
#define CP_COMMIT() asm volatile("cp.async.commit_group;" ::: "memory")
#define CP_WAIT(n)  asm volatile("cp.async.wait_group %0;" :: "n"(n) : "memory")

// mma.sync m16n8k8 tf32 (A row-major, B col-major), fp32 accumulate
#define MMA_1688(acc, a, b) \
    asm volatile("mma.sync.aligned.m16n8k8.row.col.f32.tf32.tf32.f32 " \
        "{%0,%1,%2,%3}, {%4,%5,%6,%7}, {%8,%9}, {%0,%1,%2,%3};" \
        : "+f"((acc)[0]), "+f"((acc)[1]), "+f"((acc)[2]), "+f"((acc)[3]) \
        : "r"((a)[0]), "r"((a)[1]), "r"((a)[2]), "r"((a)[3]), \
          "r"((b)[0]), "r"((b)[1]))

// ---------------- prep kernels ----------------
__global__ void round_x_kernel(const float4* __restrict__ in, float4* __restrict__ out, int n4) {
    int i = blockIdx.x * 256 + threadIdx.x;
    if (i < n4) {
        float4 v = in[i];
        v.x = rne_tf32(v.x); v.y = rne_tf32(v.y); v.z = rne_tf32(v.z); v.w = rne_tf32(v.w);
        out[i] = v;
    }
}

// g_Bc[o*128 + (n*16+r)] = rne( lora_B[n][o][r] * 2 * lw[n] )
__global__ void build_bc_kernel(const float* __restrict__ lora_B, const float* __restrict__ lw) {
    int i = blockIdx.x * 256 + threadIdx.x;
    if (i < DO * RT) {
        int o = i >> 7, c = i & 127, n = c >> 4, r = c & 15;
        g_Bc[i] = rne_tf32(lora_B[((size_t)n * DO + o) * 16 + r] * (LORA_SCALE * lw[n]));
    }
}

// g_At[d*128 + c] = rne( A_all[c][d] )   (A_all = lora_A viewed [128, 4096])
__global__ void build_at_kernel(const float* __restrict__ lora_A) {
    int i = blockIdx.x * 256 + threadIdx.x;
    if (i < DI * RT) {
        int d = i >> 7, c = i & 127;
        g_At[i] = rne_tf32(lora_A[(size_t)c * DI + d]);
    }
}

// ---------------------------------------------------------------------------
// Pipelined tf32 mma.sync GEMM:  C = A @ B^T (+bias)(+addend)(optional round)
// A: [M,K] row-major, B: [N,K] row-major, both pre-rounded to tf32. K%32==0,
// K/32 >= STAGES-1. 256 threads; CTA tile 128x128; warp tile 32x64.
// ---------------------------------------------------------------------------
__global__ __launch_bounds__(256, 1)
void tf32_gemm(const float* __restrict__ A, int lda,
               const float* __restrict__ B, int ldb, int K,
               const float* __restrict__ bias,
               const float* __restrict__ addend, int ldadd,
               float* __restrict__ C, int ldc, int round_out)
{
    extern __shared__ float smem[];
    const uint32_t sb = smem_u32(smem);

    const int tid    = threadIdx.x;
    const int lane   = tid & 31;
    const int wid    = tid >> 5;
    const int warp_m = wid & 3;          // 0..3  -> 32-row slab
    const int warp_n = wid >> 2;         // 0..1  -> 64-col slab
    const int g      = lane >> 2;        // group 0..7
    const int tg     = lane & 3;         // 0..3
    const int m0     = blockIdx.y * BM;
    const int n0     = blockIdx.x * BN;
    const int iters  = K / BK;

    // stage s: A at smem[(2s)*ST_FLOATS], B at smem[(2s+1)*ST_FLOATS]
    const int ldrow = tid >> 3;          // 0..31 base row
    const int ldck  = tid & 7;           // chunk 0..7 (16B each)

    auto load_stage = [&](int slot, int k0) {
        const uint32_t a_base = sb + (uint32_t)(2 * slot) * (ST_FLOATS * 4);
        const uint32_t b_base = a_base + ST_FLOATS * 4;
        #pragma unroll
        for (int p = 0; p < 4; p++) {
            int row = ldrow + (p << 5);
            const float* asrc = A + (size_t)(m0 + row) * lda + k0 + ldck * 4;
            CP_ASYNC16(a_base + (uint32_t)(row * (LDK * 4) + ldck * 16), asrc);
            const float* bsrc = B + (size_t)(n0 + row) * ldb + k0 + ldck * 4;
            CP_ASYNC16(b_base + (uint32_t)(row * (LDK * 4) + ldck * 16), bsrc);
        }
    };

    float acc[2][8][4];
    #pragma unroll
    for (int mt = 0; mt < 2; mt++)
        #pragma unroll
        for (int nt = 0; nt < 8; nt++)
            #pragma unroll
            for (int e = 0; e < 4; e++) acc[mt][nt][e] = 0.0f;

    // prologue: fill STAGES-1 stages
    #pragma unroll
    for (int s = 0; s < STAGES - 1; s++) { load_stage(s, s * BK); CP_COMMIT(); }

    for (int i = 0; i < iters; i++) {
        int nxt = i + STAGES - 1;
        if (nxt < iters) load_stage(nxt & (STAGES - 1), nxt * BK);
        CP_COMMIT();
        CP_WAIT(STAGES - 1);
        __syncthreads();

        const int slot = i & (STAGES - 1);
        const float* As = smem + (2 * slot) * ST_FLOATS;
        const float* Bs = As + ST_FLOATS;

        #pragma unroll
        for (int kk = 0; kk < BK; kk += 8) {
            uint32_t afr[2][4];
            #pragma unroll
            for (int mt = 0; mt < 2; mt++) {
                const float* ap = As + (warp_m * 32 + mt * 16 + g) * LDK + kk + tg;
                afr[mt][0] = __float_as_uint(ap[0]);
                afr[mt][1] = __float_as_uint(ap[8 * LDK]);
                afr[mt][2] = __float_as_uint(ap[4]);
                afr[mt][3] = __float_as_uint(ap[8 * LDK + 4]);
            }
            uint32_t bfr[8][2];
            #pragma unroll
            for (int nt = 0; nt < 8; nt++) {
                const float* bp = Bs + (warp_n * 64 + nt * 8 + g) * LDK + kk + tg;
                bfr[nt][0] = __float_as_uint(bp[0]);
                bfr[nt][1] = __float_as_uint(bp[4]);
            }
            #pragma unroll
            for (int mt = 0; mt < 2; mt++)
                #pragma unroll
                for (int nt = 0; nt < 8; nt++)
                    MMA_1688(acc[mt][nt], afr[mt], bfr[nt]);
        }
        __syncthreads();
    }

    // ---- epilogue: direct float2 stores with fused bias/addend/round ----
    #pragma unroll
    for (int mt = 0; mt < 2; mt++) {
        const int r0 = m0 + warp_m * 32 + mt * 16 + g;
        #pragma unroll
        for (int half = 0; half < 2; half++) {
            const size_t row = (size_t)(r0 + half * 8);
            #pragma unroll
            for (int nt = 0; nt < 8; nt++) {
                const int col = n0 + warp_n * 64 + nt * 8 + tg * 2;
                float v0 = acc[mt][nt][half * 2 + 0];
                float v1 = acc[mt][nt][half * 2 + 1];
                if (bias) {
                    float2 b2 = *reinterpret_cast<const float2*>(bias + col);
                    v0 += b2.x; v1 += b2.y;
                }
                if (addend) {
                    float2 a2 = *reinterpret_cast<const float2*>(addend + row * ldadd + col);
                    v0 += a2.x; v1 += a2.y;
                }
                if (round_out) { v0 = rne_tf32(v0); v1 = rne_tf32(v1); }
                *reinterpret_cast<float2*>(C + row * ldc + col) = make_float2(v0, v1);
            }
        }
    }
}

// ---------------- harness entry ----------------
extern "C" void kernel_launch(void* const* d_in, const int* in_sizes, int n_in,
                              void* d_out, int out_size)
{
    const float* x      = (const float*)d_in[0];   // [4,2048,4096]
    const float* lora_A = (const float*)d_in[1];   // [8,16,4096]
    const float* lora_B = (const float*)d_in[2];   // [8,4096,16]
    const float* W      = (const float*)d_in[3];   // [4096,4096]
    const float* bias   = (const float*)d_in[4];   // [4096]
    const float* lw     = (const float*)d_in[5];   // [8]
    float* out = (float*)d_out;

    cudaFuncSetAttribute(tf32_gemm, cudaFuncAttributeMaxDynamicSharedMemorySize, SMEM_BYTES);

    float *xr, *weff, *bc, *at;
    cudaGetSymbolAddress((void**)&xr,   g_xr);
    cudaGetSymbolAddress((void**)&weff, g_Weff);
    cudaGetSymbolAddress((void**)&bc,   g_Bc);
    cudaGetSymbolAddress((void**)&at,   g_At);

    // 1) prep: tf32-RNE rounded operands
    {
        int n4 = M_TOTAL * DI / 4;
        round_x_kernel<<<(n4 + 255) / 256, 256>>>((const float4*)x, (float4*)xr, n4);
    }
    build_bc_kernel<<<(DO * RT + 255) / 256, 256>>>(lora_B, lw);
    build_at_kernel<<<(DI * RT + 255) / 256, 256>>>(lora_A);

    // 2) W_eff = Bc @ At^T + W, rounded to tf32   [4096 x 4096], K=128
    tf32_gemm<<<dim3(DO / BN, DO / BM), 256, SMEM_BYTES>>>(
        bc, RT, at, RT, RT,
        nullptr, W, DI,
        weff, DI, 1);

    // 3) out = xr @ W_eff^T + bias   [8192 x 4096], K=4096
    tf32_gemm<<<dim3(DO / BN, M_TOTAL / BM), 256, SMEM_BYTES>>>(
        xr, DI, weff, DI, DI,
        bias, nullptr, 0,
        out, DO, 0);
}

// round 4
// speedup vs baseline: 2.3007x; 1.0815x over previous
#include <cuda_runtime.h>
#include <cstdint>

// ---------------- problem constants ----------------
#define M_TOTAL 8192
#define DI      4096
#define DO      4096
#define RT      128          // 8 adapters * rank 16
#define LORA_SCALE 2.0f      // alpha/rank

// ---------------- GEMM tiling ----------------
#define BM 128
#define BN 256
#define BK 32
#define STAGES 4
#define LDK 36                               // padded row stride (floats)
#define A_FL (BM * LDK)                      // 4608 floats / A stage
#define B_FL (BN * LDK)                      // 9216 floats / B stage
#define ST_FL (A_FL + B_FL)                  // 13824 floats / stage
#define SMEM_BYTES (STAGES * ST_FL * 4)      // 221184 B

// ---------------- scratch (allocation-free) ----------------
__device__ float g_xr  [(size_t)M_TOTAL * DI];   // x rounded to tf32 (RNE)
__device__ float g_Weff[(size_t)DO * DI];        // W + Bc@A_all, rounded to tf32
__device__ float g_Bc  [DO * RT];                // scaled lora_B, tf32
__device__ float g_At  [DI * RT];                // A_all^T, tf32

// ---------------- helpers ----------------
__device__ __forceinline__ uint32_t smem_u32(const void* p) {
    uint32_t a;
    asm("{ .reg .u64 t; cvta.to.shared.u64 t, %1; cvt.u32.u64 %0, t; }" : "=r"(a) : "l"(p));
    return a;
}
__device__ __forceinline__ float rne_tf32(float v) {
    float r; asm("cvt.rna.tf32.f32 %0, %1;" : "=f"(r) : "f"(v)); return r;
}

#define CP_ASYNC16(dst, src) \
    asm volatile("cp.async.cg.shared.global [%0], [%1], 16;" :: "r"(dst), "l"(src) : "memory")
#define CP_COMMIT() asm volatile("cp.async.commit_group;" ::: "memory")
#define CP_WAIT(n)  asm volatile("cp.async.wait_group %0;" :: "n"(n) : "memory")

// mma.sync m16n8k8 tf32 (A row-major, B col-major), fp32 accumulate
#define MMA_1688(acc, a, b) \
    asm volatile("mma.sync.aligned.m16n8k8.row.col.f32.tf32.tf32.f32 " \
        "{%0,%1,%2,%3}, {%4,%5,%6,%7}, {%8,%9}, {%0,%1,%2,%3};" \
        : "+f"((acc)[0]), "+f"((acc)[1]), "+f"((acc)[2]), "+f"((acc)[3]) \
        : "r"((a)[0]), "r"((a)[1]), "r"((a)[2]), "r"((a)[3]), \
          "r"((b)[0]), "r"((b)[1]))

// ---------------- prep kernels ----------------
__global__ void round_x_kernel(const float4* __restrict__ in, float4* __restrict__ out, int n4) {
    int i = blockIdx.x * 256 + threadIdx.x;
    if (i < n4) {
        float4 v = in[i];
        v.x = rne_tf32(v.x); v.y = rne_tf32(v.y); v.z = rne_tf32(v.z); v.w = rne_tf32(v.w);
        out[i] = v;
    }
}

// g_Bc[o*128 + (n*16+r)] = rne( lora_B[n][o][r] * 2 * lw[n] )
__global__ void build_bc_kernel(const float* __restrict__ lora_B, const float* __restrict__ lw) {
    int i = blockIdx.x * 256 + threadIdx.x;
    if (i < DO * RT) {
        int o = i >> 7, c = i & 127, n = c >> 4, r = c & 15;
        g_Bc[i] = rne_tf32(lora_B[((size_t)n * DO + o) * 16 + r] * (LORA_SCALE * lw[n]));
    }
}

// g_At[d*128 + c] = rne( A_all[c][d] )   (A_all = lora_A viewed [128, 4096])
__global__ void build_at_kernel(const float* __restrict__ lora_A) {
    int i = blockIdx.x * 256 + threadIdx.x;
    if (i < DI * RT) {
        int d = i >> 7, c = i & 127;
        g_At[i] = rne_tf32(lora_A[(size_t)c * DI + d]);
    }
}

// ---------------------------------------------------------------------------
// Pipelined tf32 mma.sync GEMM:  C = A @ B^T (+bias)(+addend)(optional round)
// A: [M,K] row-major, B: [N,K] row-major, both pre-rounded to tf32.
// K % 32 == 0, K/32 >= STAGES-1. 512 threads; CTA tile 128x256; warp 32x64.
// ---------------------------------------------------------------------------
__global__ __launch_bounds__(512, 1)
void tf32_gemm(const float* __restrict__ A, int lda,
               const float* __restrict__ B, int ldb, int K,
               const float* __restrict__ bias,
               const float* __restrict__ addend, int ldadd,
               float* __restrict__ C, int ldc, int round_out)
{
    extern __shared__ float smem[];
    const uint32_t sb = smem_u32(smem);

    const int tid    = threadIdx.x;
    const int lane   = tid & 31;
    const int wid    = tid >> 5;
    const int warp_m = wid & 3;          // 0..3 -> 32-row slab
    const int warp_n = wid >> 2;         // 0..3 -> 64-col slab
    const int g      = lane >> 2;        // 0..7
    const int tg     = lane & 3;         // 0..3
    const int m0     = blockIdx.y * BM;
    const int n0     = blockIdx.x * BN;
    const int iters  = K / BK;

    // loader mapping: 16B chunks, 8 chunks per 128B row
    const int ldrow = tid >> 3;          // 0..63
    const int ldck  = tid & 7;           // 0..7

    auto load_stage = [&](int slot, int k0) {
        const uint32_t base = sb + (uint32_t)slot * (ST_FL * 4);
        // A: 128 rows -> 1024 chunks -> 2 per thread
        #pragma unroll
        for (int p = 0; p < 2; p++) {
            int row = ldrow + (p << 6);
            const float* src = A + (size_t)(m0 + row) * lda + k0 + ldck * 4;
            CP_ASYNC16(base + (uint32_t)(row * (LDK * 4) + ldck * 16), src);
        }
        // B: 256 rows -> 2048 chunks -> 4 per thread
        const uint32_t bbase = base + A_FL * 4;
        #pragma unroll
        for (int p = 0; p < 4; p++) {
            int row = ldrow + (p << 6);
            const float* src = B + (size_t)(n0 + row) * ldb + k0 + ldck * 4;
            CP_ASYNC16(bbase + (uint32_t)(row * (LDK * 4) + ldck * 16), src);
        }
    };

    float acc[2][8][4];
    #pragma unroll
    for (int mt = 0; mt < 2; mt++)
        #pragma unroll
        for (int nt = 0; nt < 8; nt++)
            #pragma unroll
            for (int e = 0; e < 4; e++) acc[mt][nt][e] = 0.0f;

    // prologue: fill STAGES-1 stages
    #pragma unroll
    for (int s = 0; s < STAGES - 1; s++) { load_stage(s, s * BK); CP_COMMIT(); }

    for (int i = 0; i < iters; i++) {
        CP_WAIT(STAGES - 2);
        __syncthreads();   // slot i readable by all; slot (i+3)&3 writable (its last
                           // reader was iter i-1, finished before this barrier)

        int nxt = i + STAGES - 1;
        if (nxt < iters) load_stage(nxt & (STAGES - 1), nxt * BK);
        CP_COMMIT();

        const int slot = i & (STAGES - 1);
        const float* As = smem + slot * ST_FL;
        const float* Bs = As + A_FL;

        #pragma unroll
        for (int kk = 0; kk < BK; kk += 8) {
            uint32_t afr[2][4];
            #pragma unroll
            for (int mt = 0; mt < 2; mt++) {
                const float* ap = As + (warp_m * 32 + mt * 16 + g) * LDK + kk + tg;
                afr[mt][0] = __float_as_uint(ap[0]);
                afr[mt][1] = __float_as_uint(ap[8 * LDK]);
                afr[mt][2] = __float_as_uint(ap[4]);
                afr[mt][3] = __float_as_uint(ap[8 * LDK + 4]);
            }
            uint32_t bfr[8][2];
            #pragma unroll
            for (int nt = 0; nt < 8; nt++) {
                const float* bp = Bs + (warp_n * 64 + nt * 8 + g) * LDK + kk + tg;
                bfr[nt][0] = __float_as_uint(bp[0]);
                bfr[nt][1] = __float_as_uint(bp[4]);
            }
            #pragma unroll
            for (int mt = 0; mt < 2; mt++)
                #pragma unroll
                for (int nt = 0; nt < 8; nt++)
                    MMA_1688(acc[mt][nt], afr[mt], bfr[nt]);
        }
    }

    // ---- epilogue: direct float2 stores with fused bias/addend/round ----
    #pragma unroll
    for (int mt = 0; mt < 2; mt++) {
        const int r0 = m0 + warp_m * 32 + mt * 16 + g;
        #pragma unroll
        for (int half = 0; half < 2; half++) {
            const size_t row = (size_t)(r0 + half * 8);
            #pragma unroll
            for (int nt = 0; nt < 8; nt++) {
                const int col = n0 + warp_n * 64 + nt * 8 + tg * 2;
                float v0 = acc[mt][nt][half * 2 + 0];
                float v1 = acc[mt][nt][half * 2 + 1];
                if (bias) {
                    float2 b2 = *reinterpret_cast<const float2*>(bias + col);
                    v0 += b2.x; v1 += b2.y;
                }
                if (addend) {
                    float2 a2 = *reinterpret_cast<const float2*>(addend + row * ldadd + col);
                    v0 += a2.x; v1 += a2.y;
                }
                if (round_out) { v0 = rne_tf32(v0); v1 = rne_tf32(v1); }
                *reinterpret_cast<float2*>(C + row * ldc + col) = make_float2(v0, v1);
            }
        }
    }
}

// ---------------- harness entry ----------------
extern "C" void kernel_launch(void* const* d_in, const int* in_sizes, int n_in,
                              void* d_out, int out_size)
{
    const float* x      = (const float*)d_in[0];   // [4,2048,4096]
    const float* lora_A = (const float*)d_in[1];   // [8,16,4096]
    const float* lora_B = (const float*)d_in[2];   // [8,4096,16]
    const float* W      = (const float*)d_in[3];   // [4096,4096]
    const float* bias   = (const float*)d_in[4];   // [4096]
    const float* lw     = (const float*)d_in[5];   // [8]
    float* out = (float*)d_out;

    cudaFuncSetAttribute(tf32_gemm, cudaFuncAttributeMaxDynamicSharedMemorySize, SMEM_BYTES);

    float *xr, *weff, *bc, *at;
    cudaGetSymbolAddress((void**)&xr,   g_xr);
    cudaGetSymbolAddress((void**)&weff, g_Weff);
    cudaGetSymbolAddress((void**)&bc,   g_Bc);
    cudaGetSymbolAddress((void**)&at,   g_At);

    // 1) prep: tf32-RNE rounded operands
    {
        int n4 = M_TOTAL * DI / 4;
        round_x_kernel<<<(n4 + 255) / 256, 256>>>((const float4*)x, (float4*)xr, n4);
    }
    build_bc_kernel<<<(DO * RT + 255) / 256, 256>>>(lora_B, lw);
    build_at_kernel<<<(DI * RT + 255) / 256, 256>>>(lora_A);

    // 2) W_eff = Bc @ At^T + W, rounded to tf32   [4096 x 4096], K=128
    tf32_gemm<<<dim3(DO / BN, DO / BM), 512, SMEM_BYTES>>>(
        bc, RT, at, RT, RT,
        nullptr, W, DI,
        weff, DI, 1);

    // 3) out = xr @ W_eff^T + bias   [8192 x 4096], K=4096
    tf32_gemm<<<dim3(DO / BN, M_TOTAL / BM), 512, SMEM_BYTES>>>(
        xr, DI, weff, DI, DI,
        bias, nullptr, 0,
        out, DO, 0);
}

// round 5
// speedup vs baseline: 2.5323x; 1.1007x over previous
#include <cuda_runtime.h>
#include <cstdint>

// ---------------- problem constants ----------------
#define M_TOTAL 8192
#define DI      4096
#define DO      4096
#define RT      128          // 8 adapters * rank 16
#define LORA_SCALE 2.0f      // alpha/rank

// ---------------- GEMM tiling ----------------
#define BM 128
#define BN 256
#define BK 32
#define STAGES 4
#define LDK 36                               // padded row stride (floats)
#define A_FL (BM * LDK)                      // 4608 floats / A stage
#define B_FL (BN * LDK)                      // 9216 floats / B stage
#define ST_FL (A_FL + B_FL)                  // 13824 floats / stage
#define SMEM_BYTES (STAGES * ST_FL * 4)      // 221184 B

// ---------------- scratch (allocation-free) ----------------
__device__ float g_xr  [(size_t)M_TOTAL * DI];   // x rounded to tf32 (RNE)
__device__ float g_Weff[(size_t)DO * DI];        // W + Bc@A_all, rounded to tf32
__device__ float g_Bc  [DO * RT];                // scaled lora_B, tf32
__device__ float g_At  [DI * RT];                // A_all^T, tf32

// ---------------- helpers ----------------
__device__ __forceinline__ uint32_t smem_u32(const void* p) {
    uint32_t a;
    asm("{ .reg .u64 t; cvta.to.shared.u64 t, %1; cvt.u32.u64 %0, t; }" : "=r"(a) : "l"(p));
    return a;
}
__device__ __forceinline__ float rne_tf32(float v) {
    float r; asm("cvt.rna.tf32.f32 %0, %1;" : "=f"(r) : "f"(v)); return r;
}

#define CP_ASYNC16(dst, src) \
    asm volatile("cp.async.cg.shared.global [%0], [%1], 16;" :: "r"(dst), "l"(src) : "memory")
#define CP_COMMIT() asm volatile("cp.async.commit_group;" ::: "memory")
#define CP_WAIT(n)  asm volatile("cp.async.wait_group %0;" :: "n"(n) : "memory")

// ldmatrix x4 (b16 view) — one instr loads a full tf32 fragment set
#define LDSM_X4(r0, r1, r2, r3, addr) \
    asm volatile("ldmatrix.sync.aligned.m8n8.x4.shared.b16 {%0,%1,%2,%3}, [%4];" \
        : "=r"(r0), "=r"(r1), "=r"(r2), "=r"(r3) : "r"(addr))

// mma.sync m16n8k8 tf32 (A row-major, B col-major), fp32 accumulate
#define MMA_1688(acc, a0, a1, a2, a3, b0, b1) \
    asm volatile("mma.sync.aligned.m16n8k8.row.col.f32.tf32.tf32.f32 " \
        "{%0,%1,%2,%3}, {%4,%5,%6,%7}, {%8,%9}, {%0,%1,%2,%3};" \
        : "+f"((acc)[0]), "+f"((acc)[1]), "+f"((acc)[2]), "+f"((acc)[3]) \
        : "r"(a0), "r"(a1), "r"(a2), "r"(a3), "r"(b0), "r"(b1))

// ---------------- unified prep kernel (keeps launch count at 3/call) ----------------
// blocks [0, NB_X)          : round x -> g_xr   (float4 granularity)
// blocks [NB_X, NB_X+NB_BC) : build g_Bc
// blocks [.., +NB_AT)       : build g_At
#define NB_X  ((M_TOTAL * DI / 4) / 256)     // 32768
#define NB_BC ((DO * RT) / 256)              // 2048
#define NB_AT ((DI * RT) / 256)              // 2048
__global__ void prep_kernel(const float4* __restrict__ x,
                            const float* __restrict__ lora_A,
                            const float* __restrict__ lora_B,
                            const float* __restrict__ lw)
{
    const int b = blockIdx.x;
    if (b < NB_X) {
        int i = b * 256 + threadIdx.x;
        float4 v = x[i];
        v.x = rne_tf32(v.x); v.y = rne_tf32(v.y); v.z = rne_tf32(v.z); v.w = rne_tf32(v.w);
        reinterpret_cast<float4*>(g_xr)[i] = v;
    } else if (b < NB_X + NB_BC) {
        int i = (b - NB_X) * 256 + threadIdx.x;
        int o = i >> 7, c = i & 127, n = c >> 4, r = c & 15;
        g_Bc[i] = rne_tf32(lora_B[((size_t)n * DO + o) * 16 + r] * (LORA_SCALE * lw[n]));
    } else {
        int i = (b - NB_X - NB_BC) * 256 + threadIdx.x;
        int d = i >> 7, c = i & 127;
        g_At[i] = rne_tf32(lora_A[(size_t)c * DI + d]);
    }
}

// ---------------------------------------------------------------------------
// Pipelined tf32 mma.sync GEMM with ldmatrix fragment loads:
//   C = A @ B^T (+bias)(+addend)(optional round)
// A: [M,K] row-major, B: [N,K] row-major, both pre-rounded to tf32.
// K % 32 == 0, K/32 >= STAGES-1. 512 threads; CTA tile 128x256; warp 32x64.
// ---------------------------------------------------------------------------
__global__ __launch_bounds__(512, 1)
void tf32_gemm(const float* __restrict__ A, int lda,
               const float* __restrict__ B, int ldb, int K,
               const float* __restrict__ bias,
               const float* __restrict__ addend, int ldadd,
               float* __restrict__ C, int ldc, int round_out)
{
    extern __shared__ float smem[];
    const uint32_t sb = smem_u32(smem);

    const int tid    = threadIdx.x;
    const int lane   = tid & 31;
    const int wid    = tid >> 5;
    const int warp_m = wid & 3;          // 0..3 -> 32-row slab
    const int warp_n = wid >> 2;         // 0..3 -> 64-col slab
    const int g      = lane >> 2;        // 0..7
    const int tg     = lane & 3;         // 0..3
    const int m0     = blockIdx.y * BM;
    const int n0     = blockIdx.x * BN;
    const int iters  = K / BK;

    // ---- ldmatrix per-lane byte offsets (within a stage) ----
    // A (x4 -> a0..a3 of one 16-row slab): lanes 0-15 rows 0..15 col kk;
    // lanes 16-31 rows 0..15 col kk+4.
    const int aRow = lane & 15;
    const int aCol = (lane >> 4) << 2;                 // 0 or 4 floats
    uint32_t aOff[2];
    #pragma unroll
    for (int mt = 0; mt < 2; mt++)
        aOff[mt] = (uint32_t)(((warp_m * 32 + mt * 16 + aRow) * LDK + aCol) * 4);
    // B (x4 -> b0,b1 of nt and nt+1): lanes 0-7 {nt rows, kk}; 8-15 {nt rows, kk+4};
    // 16-23 {nt+1 rows, kk}; 24-31 {nt+1 rows, kk+4}.
    const int bRow = (lane & 7) + ((lane >> 4) << 3);  // 0..7 or 8..15 within pair
    const int bCol = ((lane >> 3) & 1) << 2;           // 0 or 4 floats
    uint32_t bOff[4];
    #pragma unroll
    for (int p = 0; p < 4; p++)
        bOff[p] = (uint32_t)((A_FL + (warp_n * 64 + p * 16 + bRow) * LDK + bCol) * 4);

    // loader mapping: 16B chunks, 8 chunks per 128B row
    const int ldrow = tid >> 3;          // 0..63
    const int ldck  = tid & 7;           // 0..7

    auto load_stage = [&](int slot, int k0) {
        const uint32_t base = sb + (uint32_t)slot * (ST_FL * 4);
        #pragma unroll
        for (int p = 0; p < 2; p++) {    // A: 128 rows
            int row = ldrow + (p << 6);
            const float* src = A + (size_t)(m0 + row) * lda + k0 + ldck * 4;
            CP_ASYNC16(base + (uint32_t)(row * (LDK * 4) + ldck * 16), src);
        }
        const uint32_t bbase = base + A_FL * 4;
        #pragma unroll
        for (int p = 0; p < 4; p++) {    // B: 256 rows
            int row = ldrow + (p << 6);
            const float* src = B + (size_t)(n0 + row) * ldb + k0 + ldck * 4;
            CP_ASYNC16(bbase + (uint32_t)(row * (LDK * 4) + ldck * 16), src);
        }
    };

    float acc[2][8][4];
    #pragma unroll
    for (int mt = 0; mt < 2; mt++)
        #pragma unroll
        for (int nt = 0; nt < 8; nt++)
            #pragma unroll
            for (int e = 0; e < 4; e++) acc[mt][nt][e] = 0.0f;

    // prologue
    #pragma unroll
    for (int s = 0; s < STAGES - 1; s++) { load_stage(s, s * BK); CP_COMMIT(); }

    for (int i = 0; i < iters; i++) {
        CP_WAIT(STAGES - 2);
        __syncthreads();   // slot i readable; slot (i+3)&3 writable

        int nxt = i + STAGES - 1;
        if (nxt < iters) load_stage(nxt & (STAGES - 1), nxt * BK);
        CP_COMMIT();

        const uint32_t stage = sb + (uint32_t)(i & (STAGES - 1)) * (ST_FL * 4);

        #pragma unroll
        for (int kk = 0; kk < BK; kk += 8) {
            const uint32_t kb = (uint32_t)(kk * 4);
            uint32_t af[2][4];
            #pragma unroll
            for (int mt = 0; mt < 2; mt++)
                LDSM_X4(af[mt][0], af[mt][1], af[mt][2], af[mt][3],
                        stage + aOff[mt] + kb);
            uint32_t bf[4][4];          // [pair][b0,b1 of nt | b0,b1 of nt+1]
            #pragma unroll
            for (int p = 0; p < 4; p++)
                LDSM_X4(bf[p][0], bf[p][1], bf[p][2], bf[p][3],
                        stage + bOff[p] + kb);
            #pragma unroll
            for (int mt = 0; mt < 2; mt++)
                #pragma unroll
                for (int p = 0; p < 4; p++) {
                    MMA_1688(acc[mt][2 * p + 0],
                             af[mt][0], af[mt][1], af[mt][2], af[mt][3],
                             bf[p][0], bf[p][1]);
                    MMA_1688(acc[mt][2 * p + 1],
                             af[mt][0], af[mt][1], af[mt][2], af[mt][3],
                             bf[p][2], bf[p][3]);
                }
        }
    }

    // ---- epilogue: direct float2 stores with fused bias/addend/round ----
    #pragma unroll
    for (int mt = 0; mt < 2; mt++) {
        const int r0 = m0 + warp_m * 32 + mt * 16 + g;
        #pragma unroll
        for (int half = 0; half < 2; half++) {
            const size_t row = (size_t)(r0 + half * 8);
            #pragma unroll
            for (int nt = 0; nt < 8; nt++) {
                const int col = n0 + warp_n * 64 + nt * 8 + tg * 2;
                float v0 = acc[mt][nt][half * 2 + 0];
                float v1 = acc[mt][nt][half * 2 + 1];
                if (bias) {
                    float2 b2 = *reinterpret_cast<const float2*>(bias + col);
                    v0 += b2.x; v1 += b2.y;
                }
                if (addend) {
                    float2 a2 = *reinterpret_cast<const float2*>(addend + row * ldadd + col);
                    v0 += a2.x; v1 += a2.y;
                }
                if (round_out) { v0 = rne_tf32(v0); v1 = rne_tf32(v1); }
                *reinterpret_cast<float2*>(C + row * ldc + col) = make_float2(v0, v1);
            }
        }
    }
}

// ---------------- harness entry ----------------
extern "C" void kernel_launch(void* const* d_in, const int* in_sizes, int n_in,
                              void* d_out, int out_size)
{
    const float* x      = (const float*)d_in[0];   // [4,2048,4096]
    const float* lora_A = (const float*)d_in[1];   // [8,16,4096]
    const float* lora_B = (const float*)d_in[2];   // [8,4096,16]
    const float* W      = (const float*)d_in[3];   // [4096,4096]
    const float* bias   = (const float*)d_in[4];   // [4096]
    const float* lw     = (const float*)d_in[5];   // [8]
    float* out = (float*)d_out;

    cudaFuncSetAttribute(tf32_gemm, cudaFuncAttributeMaxDynamicSharedMemorySize, SMEM_BYTES);

    float *xr, *weff, *bc, *at;
    cudaGetSymbolAddress((void**)&xr,   g_xr);
    cudaGetSymbolAddress((void**)&weff, g_Weff);
    cudaGetSymbolAddress((void**)&bc,   g_Bc);
    cudaGetSymbolAddress((void**)&at,   g_At);

    // 1) unified prep (1 launch): round x, build Bc, build At
    prep_kernel<<<NB_X + NB_BC + NB_AT, 256>>>((const float4*)x, lora_A, lora_B, lw);

    // 2) W_eff = Bc @ At^T + W, rounded to tf32   [4096 x 4096], K=128
    tf32_gemm<<<dim3(DO / BN, DO / BM), 512, SMEM_BYTES>>>(
        bc, RT, at, RT, RT,
        nullptr, W, DI,
        weff, DI, 1);

    // 3) out = xr @ W_eff^T + bias   [8192 x 4096], K=4096
    tf32_gemm<<<dim3(DO / BN, M_TOTAL / BM), 512, SMEM_BYTES>>>(
        xr, DI, weff, DI, DI,
        bias, nullptr, 0,
        out, DO, 0);
}

// round 6
// speedup vs baseline: 4.4218x; 1.7461x over previous
#include <cuda_runtime.h>
#include <cuda_fp16.h>
#include <cstdint>

// ---------------- problem constants ----------------
#define M_TOTAL 8192
#define DI      4096
#define DO      4096
#define RT      128          // 8 adapters * rank 16
#define LORA_SCALE 2.0f      // alpha/rank

// ---------------- GEMM tiling (fp16 operands, fp32 accum) ----------------
#define BM 128
#define BN 256
#define BK 32
#define STAGES 4
#define LDKH 40                              // padded row stride in halfs (80 B, LDSM conflict-free)
#define A_HB (BM * LDKH * 2)                 // 10240 B per A stage
#define B_HB (BN * LDKH * 2)                 // 20480 B per B stage
#define ST_HB (A_HB + B_HB)                  // 30720 B per stage
#define SMEM_BYTES (STAGES * ST_HB)          // 122880 B

// ---------------- scratch (allocation-free) ----------------
__device__ __half g_xh   [(size_t)M_TOTAL * DI];   // x rounded to fp16 (RNE)
__device__ __half g_Weffh[(size_t)DO * DI];        // W + Bc@A_all, rounded to fp16
__device__ __half g_Bch  [DO * RT];                // scaled lora_B, fp16
__device__ __half g_Ath  [DI * RT];                // A_all^T, fp16

// ---------------- helpers ----------------
__device__ __forceinline__ uint32_t smem_u32(const void* p) {
    uint32_t a;
    asm("{ .reg .u64 t; cvta.to.shared.u64 t, %1; cvt.u32.u64 %0, t; }" : "=r"(a) : "l"(p));
    return a;
}

#define CP_ASYNC16(dst, src) \
    asm volatile("cp.async.cg.shared.global [%0], [%1], 16;" :: "r"(dst), "l"(src) : "memory")
#define CP_COMMIT() asm volatile("cp.async.commit_group;" ::: "memory")
#define CP_WAIT(n)  asm volatile("cp.async.wait_group %0;" :: "n"(n) : "memory")

#define LDSM_X4(r0, r1, r2, r3, addr) \
    asm volatile("ldmatrix.sync.aligned.m8n8.x4.shared.b16 {%0,%1,%2,%3}, [%4];" \
        : "=r"(r0), "=r"(r1), "=r"(r2), "=r"(r3) : "r"(addr))

// mma.sync m16n8k16 fp16 (A row-major, B col-major), fp32 accumulate
#define MMA_16816(acc, a0, a1, a2, a3, b0, b1) \
    asm volatile("mma.sync.aligned.m16n8k16.row.col.f32.f16.f16.f32 " \
        "{%0,%1,%2,%3}, {%4,%5,%6,%7}, {%8,%9}, {%0,%1,%2,%3};" \
        : "+f"((acc)[0]), "+f"((acc)[1]), "+f"((acc)[2]), "+f"((acc)[3]) \
        : "r"(a0), "r"(a1), "r"(a2), "r"(a3), "r"(b0), "r"(b1))

// ---------------- unified prep kernel ----------------
// blocks [0, NB_X)          : round x -> g_xh   (4 floats / thread)
// blocks [NB_X, NB_X+NB_BC) : build g_Bch
// blocks [.., +NB_AT)       : build g_Ath
#define NB_X  ((M_TOTAL * DI / 4) / 256)     // 32768
#define NB_BC ((DO * RT) / 256)              // 2048
#define NB_AT ((DI * RT) / 256)              // 2048
__global__ void prep_kernel(const float4* __restrict__ x,
                            const float* __restrict__ lora_A,
                            const float* __restrict__ lora_B,
                            const float* __restrict__ lw)
{
    const int b = blockIdx.x;
    if (b < NB_X) {
        int i = b * 256 + threadIdx.x;
        float4 v = x[i];
        __half2* o = reinterpret_cast<__half2*>(g_xh) + i * 2;
        o[0] = __floats2half2_rn(v.x, v.y);
        o[1] = __floats2half2_rn(v.z, v.w);
    } else if (b < NB_X + NB_BC) {
        int i = (b - NB_X) * 256 + threadIdx.x;
        int o = i >> 7, c = i & 127, n = c >> 4, r = c & 15;
        g_Bch[i] = __float2half_rn(lora_B[((size_t)n * DO + o) * 16 + r] * (LORA_SCALE * lw[n]));
    } else {
        int i = (b - NB_X - NB_BC) * 256 + threadIdx.x;
        int d = i >> 7, c = i & 127;
        g_Ath[i] = __float2half_rn(lora_A[(size_t)c * DI + d]);
    }
}

// ---------------------------------------------------------------------------
// Pipelined fp16 mma.sync GEMM:  C = A @ B^T (+bias)(+addend fp32)
// A: [M,K] row-major fp16, B: [N,K] row-major fp16.  K % 32 == 0, K/32 >= 3.
// Output: if Ch != null -> fp16 (RNE); else fp32 to Cf.
// 512 threads; CTA tile 128x256; warp tile 32x64.
// ---------------------------------------------------------------------------
__global__ __launch_bounds__(512, 1)
void h16_gemm(const __half* __restrict__ A, int lda,
              const __half* __restrict__ B, int ldb, int K,
              const float* __restrict__ bias,
              const float* __restrict__ addend, int ldadd,
              float* __restrict__ Cf, __half* __restrict__ Ch, int ldc)
{
    extern __shared__ char smem[];
    const uint32_t sb = smem_u32(smem);

    const int tid    = threadIdx.x;
    const int lane   = tid & 31;
    const int wid    = tid >> 5;
    const int warp_m = wid & 3;          // 0..3 -> 32-row slab
    const int warp_n = wid >> 2;         // 0..3 -> 64-col slab
    const int g      = lane >> 2;        // 0..7
    const int tg     = lane & 3;         // 0..3
    const int m0     = blockIdx.y * BM;
    const int n0     = blockIdx.x * BN;
    const int iters  = K / BK;

    // ---- ldmatrix per-lane byte offsets within a stage ----
    // A x4: lanes 0-15 -> rows 0..15 at k-chunk 0 (16B); lanes 16-31 -> rows at +16B.
    const int aRow = lane & 15;
    uint32_t aOff[2];
    #pragma unroll
    for (int mt = 0; mt < 2; mt++)
        aOff[mt] = (uint32_t)((warp_m * 32 + mt * 16 + aRow) * (LDKH * 2) + ((lane >> 4) << 4));
    // B x4 (nt-pair): lanes 0-7 {nt rows, +0B}; 8-15 {nt rows, +16B};
    //                 16-23 {nt+1 rows, +0B}; 24-31 {nt+1 rows, +16B}.
    const int bRow = (lane & 7) + ((lane >> 4) << 3);
    uint32_t bOff[4];
    #pragma unroll
    for (int p = 0; p < 4; p++)
        bOff[p] = (uint32_t)(A_HB + (warp_n * 64 + p * 16 + bRow) * (LDKH * 2) + (((lane >> 3) & 1) << 4));

    // ---- loaders: 16B chunks (8 halfs); 4 chunks per 64B k32-row ----
    auto load_stage = [&](int slot, int k0) {
        const uint32_t base = sb + (uint32_t)slot * ST_HB;
        {   // A: 128 rows x 4 chunks = 512 -> 1/thread
            int row = tid >> 2, ck = tid & 3;
            const __half* src = A + (size_t)(m0 + row) * lda + k0 + ck * 8;
            CP_ASYNC16(base + (uint32_t)(row * (LDKH * 2) + ck * 16), src);
        }
        const uint32_t bbase = base + A_HB;
        #pragma unroll
        for (int p = 0; p < 2; p++) {  // B: 256 rows x 4 chunks = 1024 -> 2/thread
            int idx = tid + (p << 9);
            int row = idx >> 2, ck = idx & 3;
            const __half* src = B + (size_t)(n0 + row) * ldb + k0 + ck * 8;
            CP_ASYNC16(bbase + (uint32_t)(row * (LDKH * 2) + ck * 16), src);
        }
    };

    float acc[2][8][4];
    #pragma unroll
    for (int mt = 0; mt < 2; mt++)
        #pragma unroll
        for (int nt = 0; nt < 8; nt++)
            #pragma unroll
            for (int e = 0; e < 4; e++) acc[mt][nt][e] = 0.0f;

    // prologue
    #pragma unroll
    for (int s = 0; s < STAGES - 1; s++) { load_stage(s, s * BK); CP_COMMIT(); }

    for (int i = 0; i < iters; i++) {
        CP_WAIT(STAGES - 2);
        __syncthreads();   // slot i readable; slot (i+3)&3 writable

        int nxt = i + STAGES - 1;
        if (nxt < iters) load_stage(nxt & (STAGES - 1), nxt * BK);
        CP_COMMIT();

        const uint32_t stage = sb + (uint32_t)(i & (STAGES - 1)) * ST_HB;

        #pragma unroll
        for (int kk = 0; kk < 2; kk++) {             // two k16 steps per iter
            const uint32_t kb = (uint32_t)(kk * 32); // 16 halfs = 32 B
            uint32_t af[2][4];
            #pragma unroll
            for (int mt = 0; mt < 2; mt++)
                LDSM_X4(af[mt][0], af[mt][1], af[mt][2], af[mt][3], stage + aOff[mt] + kb);
            uint32_t bf[4][4];
            #pragma unroll
            for (int p = 0; p < 4; p++)
                LDSM_X4(bf[p][0], bf[p][1], bf[p][2], bf[p][3], stage + bOff[p] + kb);
            #pragma unroll
            for (int mt = 0; mt < 2; mt++)
                #pragma unroll
                for (int p = 0; p < 4; p++) {
                    MMA_16816(acc[mt][2 * p + 0],
                              af[mt][0], af[mt][1], af[mt][2], af[mt][3],
                              bf[p][0], bf[p][1]);
                    MMA_16816(acc[mt][2 * p + 1],
                              af[mt][0], af[mt][1], af[mt][2], af[mt][3],
                              bf[p][2], bf[p][3]);
                }
        }
    }

    // ---- epilogue ----
    #pragma unroll
    for (int mt = 0; mt < 2; mt++) {
        const int r0 = m0 + warp_m * 32 + mt * 16 + g;
        #pragma unroll
        for (int half_ = 0; half_ < 2; half_++) {
            const size_t row = (size_t)(r0 + half_ * 8);
            #pragma unroll
            for (int nt = 0; nt < 8; nt++) {
                const int col = n0 + warp_n * 64 + nt * 8 + tg * 2;
                float v0 = acc[mt][nt][half_ * 2 + 0];
                float v1 = acc[mt][nt][half_ * 2 + 1];
                if (bias) {
                    float2 b2 = *reinterpret_cast<const float2*>(bias + col);
                    v0 += b2.x; v1 += b2.y;
                }
                if (addend) {
                    float2 a2 = *reinterpret_cast<const float2*>(addend + row * ldadd + col);
                    v0 += a2.x; v1 += a2.y;
                }
                if (Ch) {
                    *reinterpret_cast<__half2*>(Ch + row * ldc + col) = __floats2half2_rn(v0, v1);
                } else {
                    *reinterpret_cast<float2*>(Cf + row * ldc + col) = make_float2(v0, v1);
                }
            }
        }
    }
}

// ---------------- harness entry ----------------
extern "C" void kernel_launch(void* const* d_in, const int* in_sizes, int n_in,
                              void* d_out, int out_size)
{
    const float* x      = (const float*)d_in[0];   // [4,2048,4096]
    const float* lora_A = (const float*)d_in[1];   // [8,16,4096]
    const float* lora_B = (const float*)d_in[2];   // [8,4096,16]
    const float* W      = (const float*)d_in[3];   // [4096,4096]
    const float* bias   = (const float*)d_in[4];   // [4096]
    const float* lw     = (const float*)d_in[5];   // [8]
    float* out = (float*)d_out;

    cudaFuncSetAttribute(h16_gemm, cudaFuncAttributeMaxDynamicSharedMemorySize, SMEM_BYTES);

    __half *xh, *weffh, *bch, *ath;
    cudaGetSymbolAddress((void**)&xh,    g_xh);
    cudaGetSymbolAddress((void**)&weffh, g_Weffh);
    cudaGetSymbolAddress((void**)&bch,   g_Bch);
    cudaGetSymbolAddress((void**)&ath,   g_Ath);

    // 1) unified prep: round x -> fp16, build Bc/At fp16
    prep_kernel<<<NB_X + NB_BC + NB_AT, 256>>>((const float4*)x, lora_A, lora_B, lw);

    // 2) W_eff = Bc @ At^T + W  -> fp16   [4096 x 4096], K=128
    h16_gemm<<<dim3(DO / BN, DO / BM), 512, SMEM_BYTES>>>(
        bch, RT, ath, RT, RT,
        nullptr, W, DI,
        nullptr, weffh, DI);

    // 3) out = xh @ W_eff^T + bias   [8192 x 4096], K=4096, fp32 out
    h16_gemm<<<dim3(DO / BN, M_TOTAL / BM), 512, SMEM_BYTES>>>(
        xh, DI, weffh, DI, DI,
        bias, nullptr, 0,
        out, nullptr, DO);
}

// round 7
// speedup vs baseline: 4.7114x; 1.0655x over previous
#include <cuda_runtime.h>
#include <cuda_fp16.h>
#include <cstdint>

// ---------------- problem constants ----------------
#define M_TOTAL 8192
#define DI      4096
#define DO      4096
#define RT      128          // 8 adapters * rank 16
#define LORA_SCALE 2.0f      // alpha/rank

// ---------------- GEMM tiling (fp16 operands, fp32 accum) ----------------
#define BM 128
#define BN 256
#define BK 64
#define STAGES 4
#define LDKH 72                              // padded row stride in halfs (144 B; ldmatrix rows -> banks 4r mod 32, conflict-free)
#define A_HB (BM * LDKH * 2)                 // 18432 B per A stage
#define B_HB (BN * LDKH * 2)                 // 36864 B per B stage
#define ST_HB (A_HB + B_HB)                  // 55296 B per stage
#define SMEM_BYTES (STAGES * ST_HB)          // 221184 B

// ---------------- scratch (allocation-free) ----------------
__device__ __half g_xh   [(size_t)M_TOTAL * DI];   // x rounded to fp16 (RNE)
__device__ __half g_Weffh[(size_t)DO * DI];        // W + Bc@A_all, rounded to fp16
__device__ __half g_Bch  [DO * RT];                // scaled lora_B, fp16
__device__ __half g_Ath  [DI * RT];                // A_all^T, fp16

// ---------------- helpers ----------------
__device__ __forceinline__ uint32_t smem_u32(const void* p) {
    uint32_t a;
    asm("{ .reg .u64 t; cvta.to.shared.u64 t, %1; cvt.u32.u64 %0, t; }" : "=r"(a) : "l"(p));
    return a;
}

#define CP_ASYNC16(dst, src) \
    asm volatile("cp.async.cg.shared.global [%0], [%1], 16;" :: "r"(dst), "l"(src) : "memory")
#define CP_COMMIT() asm volatile("cp.async.commit_group;" ::: "memory")
#define CP_WAIT(n)  asm volatile("cp.async.wait_group %0;" :: "n"(n) : "memory")

#define LDSM_X4(r0, r1, r2, r3, addr) \
    asm volatile("ldmatrix.sync.aligned.m8n8.x4.shared.b16 {%0,%1,%2,%3}, [%4];" \
        : "=r"(r0), "=r"(r1), "=r"(r2), "=r"(r3) : "r"(addr))

// mma.sync m16n8k16 fp16 (A row-major, B col-major), fp32 accumulate
#define MMA_16816(acc, a0, a1, a2, a3, b0, b1) \
    asm volatile("mma.sync.aligned.m16n8k16.row.col.f32.f16.f16.f32 " \
        "{%0,%1,%2,%3}, {%4,%5,%6,%7}, {%8,%9}, {%0,%1,%2,%3};" \
        : "+f"((acc)[0]), "+f"((acc)[1]), "+f"((acc)[2]), "+f"((acc)[3]) \
        : "r"(a0), "r"(a1), "r"(a2), "r"(a3), "r"(b0), "r"(b1))

// ---------------- unified prep kernel ----------------
#define NB_X  ((M_TOTAL * DI / 4) / 256)     // 32768
#define NB_BC ((DO * RT) / 256)              // 2048
#define NB_AT ((DI * RT) / 256)              // 2048
__global__ void prep_kernel(const float4* __restrict__ x,
                            const float* __restrict__ lora_A,
                            const float* __restrict__ lora_B,
                            const float* __restrict__ lw)
{
    const int b = blockIdx.x;
    if (b < NB_X) {
        int i = b * 256 + threadIdx.x;
        float4 v = x[i];
        __half2* o = reinterpret_cast<__half2*>(g_xh) + i * 2;
        o[0] = __floats2half2_rn(v.x, v.y);
        o[1] = __floats2half2_rn(v.z, v.w);
    } else if (b < NB_X + NB_BC) {
        int i = (b - NB_X) * 256 + threadIdx.x;
        int o = i >> 7, c = i & 127, n = c >> 4, r = c & 15;
        g_Bch[i] = __float2half_rn(lora_B[((size_t)n * DO + o) * 16 + r] * (LORA_SCALE * lw[n]));
    } else {
        int i = (b - NB_X - NB_BC) * 256 + threadIdx.x;
        int d = i >> 7, c = i & 127;
        g_Ath[i] = __float2half_rn(lora_A[(size_t)c * DI + d]);
    }
}

// ---------------------------------------------------------------------------
// Pipelined fp16 mma.sync GEMM:  C = A @ B^T (+bias)(+addend fp32)
// A: [M,K] row-major fp16, B: [N,K] row-major fp16.  K % 64 == 0.
// Output: if Ch != null -> fp16 (RNE); else fp32 to Cf.
// 256 threads / 8 warps; CTA tile 128x256; warp tile 64x64 (2 m-warps x 4 n-warps).
// ---------------------------------------------------------------------------
__global__ __launch_bounds__(256, 1)
void h16_gemm(const __half* __restrict__ A, int lda,
              const __half* __restrict__ B, int ldb, int K,
              const float* __restrict__ bias,
              const float* __restrict__ addend, int ldadd,
              float* __restrict__ Cf, __half* __restrict__ Ch, int ldc)
{
    extern __shared__ char smem[];
    const uint32_t sb = smem_u32(smem);

    const int tid    = threadIdx.x;
    const int lane   = tid & 31;
    const int wid    = tid >> 5;
    const int warp_m = wid & 1;          // 0..1 -> 64-row slab
    const int warp_n = wid >> 1;         // 0..3 -> 64-col slab
    const int g      = lane >> 2;        // 0..7
    const int tg     = lane & 3;         // 0..3
    const int m0     = blockIdx.y * BM;
    const int n0     = blockIdx.x * BN;
    const int iters  = K / BK;

    // ---- ldmatrix per-lane byte offsets within a stage ----
    // A x4: lanes 0-15 -> 16 rows at +0B; lanes 16-31 -> same rows at +16B.
    const int aRow = lane & 15;
    uint32_t aOff[4];
    #pragma unroll
    for (int mt = 0; mt < 4; mt++)
        aOff[mt] = (uint32_t)((warp_m * 64 + mt * 16 + aRow) * (LDKH * 2) + ((lane >> 4) << 4));
    // B x4 (nt-pair): lanes 0-7 {nt rows,+0B}; 8-15 {nt rows,+16B};
    //                 16-23 {nt+1 rows,+0B}; 24-31 {nt+1 rows,+16B}.
    const int bRow = (lane & 7) + ((lane >> 4) << 3);
    uint32_t bOff[4];
    #pragma unroll
    for (int p = 0; p < 4; p++)
        bOff[p] = (uint32_t)(A_HB + (warp_n * 64 + p * 16 + bRow) * (LDKH * 2) + (((lane >> 3) & 1) << 4));

    // ---- loaders: 16B chunks (8 halfs); 8 chunks per 128B k64-row ----
    auto load_stage = [&](int slot, int k0) {
        const uint32_t base = sb + (uint32_t)slot * ST_HB;
        #pragma unroll
        for (int p = 0; p < 4; p++) {    // A: 128 rows x 8 chunks = 1024 -> 4/thread
            int idx = tid + (p << 8);
            int row = idx >> 3, ck = idx & 7;
            const __half* src = A + (size_t)(m0 + row) * lda + k0 + ck * 8;
            CP_ASYNC16(base + (uint32_t)(row * (LDKH * 2) + ck * 16), src);
        }
        const uint32_t bbase = base + A_HB;
        #pragma unroll
        for (int p = 0; p < 8; p++) {    // B: 256 rows x 8 chunks = 2048 -> 8/thread
            int idx = tid + (p << 8);
            int row = idx >> 3, ck = idx & 7;
            const __half* src = B + (size_t)(n0 + row) * ldb + k0 + ck * 8;
            CP_ASYNC16(bbase + (uint32_t)(row * (LDKH * 2) + ck * 16), src);
        }
    };

    float acc[4][8][4];
    #pragma unroll
    for (int mt = 0; mt < 4; mt++)
        #pragma unroll
        for (int nt = 0; nt < 8; nt++)
            #pragma unroll
            for (int e = 0; e < 4; e++) acc[mt][nt][e] = 0.0f;

    // prologue (guarded: W_eff GEMM has iters=2 < STAGES-1)
    #pragma unroll
    for (int s = 0; s < STAGES - 1; s++) {
        if (s < iters) load_stage(s, s * BK);
        CP_COMMIT();
    }

    for (int i = 0; i < iters; i++) {
        CP_WAIT(STAGES - 2);
        __syncthreads();   // slot i readable; slot (i+3)&3 writable

        int nxt = i + STAGES - 1;
        if (nxt < iters) load_stage(nxt & (STAGES - 1), nxt * BK);
        CP_COMMIT();

        const uint32_t stage = sb + (uint32_t)(i & (STAGES - 1)) * ST_HB;

        #pragma unroll
        for (int kk = 0; kk < BK / 16; kk++) {       // four k16 steps per iter
            const uint32_t kb = (uint32_t)(kk * 32); // 16 halfs = 32 B
            uint32_t af[4][4];
            #pragma unroll
            for (int mt = 0; mt < 4; mt++)
                LDSM_X4(af[mt][0], af[mt][1], af[mt][2], af[mt][3], stage + aOff[mt] + kb);
            uint32_t bf[4][4];
            #pragma unroll
            for (int p = 0; p < 4; p++)
                LDSM_X4(bf[p][0], bf[p][1], bf[p][2], bf[p][3], stage + bOff[p] + kb);
            #pragma unroll
            for (int mt = 0; mt < 4; mt++)
                #pragma unroll
                for (int p = 0; p < 4; p++) {
                    MMA_16816(acc[mt][2 * p + 0],
                              af[mt][0], af[mt][1], af[mt][2], af[mt][3],
                              bf[p][0], bf[p][1]);
                    MMA_16816(acc[mt][2 * p + 1],
                              af[mt][0], af[mt][1], af[mt][2], af[mt][3],
                              bf[p][2], bf[p][3]);
                }
        }
    }

    // ---- epilogue ----
    #pragma unroll
    for (int mt = 0; mt < 4; mt++) {
        const int r0 = m0 + warp_m * 64 + mt * 16 + g;
        #pragma unroll
        for (int half_ = 0; half_ < 2; half_++) {
            const size_t row = (size_t)(r0 + half_ * 8);
            #pragma unroll
            for (int nt = 0; nt < 8; nt++) {
                const int col = n0 + warp_n * 64 + nt * 8 + tg * 2;
                float v0 = acc[mt][nt][half_ * 2 + 0];
                float v1 = acc[mt][nt][half_ * 2 + 1];
                if (bias) {
                    float2 b2 = *reinterpret_cast<const float2*>(bias + col);
                    v0 += b2.x; v1 += b2.y;
                }
                if (addend) {
                    float2 a2 = *reinterpret_cast<const float2*>(addend + row * ldadd + col);
                    v0 += a2.x; v1 += a2.y;
                }
                if (Ch) {
                    *reinterpret_cast<__half2*>(Ch + row * ldc + col) = __floats2half2_rn(v0, v1);
                } else {
                    *reinterpret_cast<float2*>(Cf + row * ldc + col) = make_float2(v0, v1);
                }
            }
        }
    }
}

// ---------------- harness entry ----------------
extern "C" void kernel_launch(void* const* d_in, const int* in_sizes, int n_in,
                              void* d_out, int out_size)
{
    const float* x      = (const float*)d_in[0];   // [4,2048,4096]
    const float* lora_A = (const float*)d_in[1];   // [8,16,4096]
    const float* lora_B = (const float*)d_in[2];   // [8,4096,16]
    const float* W      = (const float*)d_in[3];   // [4096,4096]
    const float* bias   = (const float*)d_in[4];   // [4096]
    const float* lw     = (const float*)d_in[5];   // [8]
    float* out = (float*)d_out;

    cudaFuncSetAttribute(h16_gemm, cudaFuncAttributeMaxDynamicSharedMemorySize, SMEM_BYTES);

    __half *xh, *weffh, *bch, *ath;
    cudaGetSymbolAddress((void**)&xh,    g_xh);
    cudaGetSymbolAddress((void**)&weffh, g_Weffh);
    cudaGetSymbolAddress((void**)&bch,   g_Bch);
    cudaGetSymbolAddress((void**)&ath,   g_Ath);

    // 1) unified prep: round x -> fp16, build Bc/At fp16
    prep_kernel<<<NB_X + NB_BC + NB_AT, 256>>>((const float4*)x, lora_A, lora_B, lw);

    // 2) W_eff = Bc @ At^T + W  -> fp16   [4096 x 4096], K=128
    h16_gemm<<<dim3(DO / BN, DO / BM), 256, SMEM_BYTES>>>(
        bch, RT, ath, RT, RT,
        nullptr, W, DI,
        nullptr, weffh, DI);

    // 3) out = xh @ W_eff^T + bias   [8192 x 4096], K=4096, fp32 out
    h16_gemm<<<dim3(DO / BN, M_TOTAL / BM), 256, SMEM_BYTES>>>(
        xh, DI, weffh, DI, DI,
        bias, nullptr, 0,
        out, nullptr, DO);
}